// round 6
// baseline (speedup 1.0000x reference)
#include <cuda_runtime.h>

// Problem constants (fixed shapes from the reference)
#define N_NODES   100000
#define NFEATS    256
#define HIDDEN    128
#define NCLASS    64
#define BATCH     1024
#define K0        25
#define K1        10
#define NHIST     5
#define ROWS_TOTAL (BATCH + BATCH * K1)   // 11264 layer0 rows
#define RPB        32                      // rows per block
#define NBLK       (ROWS_TOTAL / RPB)      // 352 blocks (single wave)
#define FB         8                       // roots per block in final kernel
#define FNBLK      (BATCH / FB)            // 128 blocks

// Scratch: layer0 outputs. rows [0,1024) = h1, rows [1024,11264) = neigh_original.
__device__ float g_L0[(size_t)ROWS_TOTAL * HIDDEN];
// Pre-packed W0: g_W0p[kp*128 + t] = ( W0[2kp][t], W0[2kp+1][t] )
__device__ float2 g_W0p[(2 * NFEATS / 2) * HIDDEN];   // 256*128 float2 = 256 KB

// ---- packed f32x2 helpers (Blackwell FFMA2; ptxas never emits these from C++) ----
__device__ __forceinline__ unsigned long long pack2(float lo, float hi) {
    unsigned long long r;
    asm("mov.b64 %0, {%1, %2};" : "=l"(r) : "f"(lo), "f"(hi));
    return r;
}
__device__ __forceinline__ void unpack2(unsigned long long v, float& lo, float& hi) {
    asm("mov.b64 {%0, %1}, %2;" : "=f"(lo), "=f"(hi) : "l"(v));
}
__device__ __forceinline__ void fma2(unsigned long long& d, unsigned long long a,
                                     unsigned long long b) {
    asm("fma.rn.f32x2 %0, %1, %2, %0;" : "+l"(d) : "l"(a), "l"(b));
}

// ============================================================================
// Kernel 0: pack W0 column-pairs so the GEMV loads one coalesced LDG.64 per
// two k-steps instead of two strided LDG.32.
// ============================================================================
__global__ __launch_bounds__(256)
void w0pack_kernel(const float* __restrict__ W0)
{
    const int i  = blockIdx.x * blockDim.x + threadIdx.x;  // 0..32767
    const int kp = i >> 7;
    const int t  = i & 127;
    g_W0p[i] = make_float2(W0[(size_t)(2 * kp) * HIDDEN + t],
                           W0[(size_t)(2 * kp + 1) * HIDDEN + t]);
}

// ============================================================================
// Kernel 1: fused gather-mean + [512]x[512,128] GEMV + bias + ReLU
// for all 11264 layer0 rows. 256 threads, 32 rows per block.
//
// Warp-group g = tid>>7 (0/1):
//   Phase 1: group g gathers rows [16g, 16g+16) of the block (128 threads/row,
//            float2-coalesced), storing into the row-pair-interleaved smem:
//            xs[p][k] = float2( x[row 2p][k], x[row 2p+1][k] ), k in [0,512)
//   Phase 2: split-K GEMV — group g covers k in [256g, 256g+256) for ALL 16
//            row-pairs, with packed FFMA2 (2 FMA / instr).
//   Reduce:  group 1 stores its packed partials to smem, group 0 combines,
//            adds bias, ReLU, writes scratch.
// Dynamic smem: 64 KB (16 x 512 float2).
// ============================================================================
__global__ __launch_bounds__(256)
void layer0_kernel(const float* __restrict__ feats,
                   const float* __restrict__ b0,
                   const int*   __restrict__ nodes,
                   const int*   __restrict__ neighs0,
                   const int*   __restrict__ neighs1,
                   const int*   __restrict__ neighs0_nb)
{
    extern __shared__ float2 xs_raw[];
    float2 (*xs)[2 * NFEATS] = (float2(*)[2 * NFEATS])xs_raw;  // [16][512]

    const int t    = threadIdx.x & 127;   // feature column pair: cols 2t, 2t+1
    const int g    = threadIdx.x >> 7;    // warp-group
    const int row0 = blockIdx.x * RPB;
    const float2* f2 = (const float2*)feats;

    // ---------------- Phase 1: gather + mean (16 rows per group) ----------------
    #pragma unroll 1
    for (int i = 0; i < RPB / 2; i++) {
        const int r   = g * (RPB / 2) + i;
        const int row = row0 + r;
        int self;
        const int* nb;
        if (row < BATCH) {                  // root rows: nodes / neighs0
            self = nodes[row];
            nb   = neighs0 + row * K0;
        } else {                            // neighbor rows: neighs1 / neighs0_nb
            const int j = row - BATCH;
            self = neighs1[j];
            nb   = neighs0_nb + j * K0;
        }
        const float2 sv = f2[(size_t)self * (NFEATS / 2) + t];
        float sx = 0.f, sy = 0.f;
        #pragma unroll
        for (int k = 0; k < K0; k++) {
            const float2 v = f2[(size_t)nb[k] * (NFEATS / 2) + t];
            sx += v.x; sy += v.y;
        }
        sx *= (1.f / K0);
        sy *= (1.f / K0);

        // interleaved store: float index = k*2 + (r&1) within pair p = r>>1
        float* base = (float*)&xs[r >> 1][0];
        const int lane = r & 1;
        base[4 * t + lane]                   = sv.x;   // k = 2t
        base[4 * t + 2 + lane]               = sv.y;   // k = 2t+1
        base[2 * NFEATS + 4 * t + lane]      = sx;     // k = 256+2t
        base[2 * NFEATS + 4 * t + 2 + lane]  = sy;     // k = 256+2t+1
    }
    __syncthreads();

    // ---------------- Phase 2: split-K GEMV with packed FFMA2 ----------------
    unsigned long long acc[RPB / 2];
    #pragma unroll
    for (int p = 0; p < RPB / 2; p++) acc[p] = 0ull;   // bit pattern (0.f, 0.f)

    const float2* wbase = g_W0p + (size_t)(128 * g) * HIDDEN + t;
    #pragma unroll 2
    for (int kp = 0; kp < 128; kp++) {
        const float2 w = wbase[(size_t)kp * HIDDEN];       // coalesced LDG.64
        const unsigned long long w0d = pack2(w.x, w.x);
        const unsigned long long w1d = pack2(w.y, w.y);
        const int kf = NFEATS * g + 2 * kp;                // feature index
        #pragma unroll
        for (int p = 0; p < RPB / 2; p++) {
            const ulonglong2 xv = *(const ulonglong2*)&xs[p][kf];  // 16B smem bcast
            fma2(acc[p], xv.x, w0d);   // feature kf
            fma2(acc[p], xv.y, w1d);   // feature kf+1
        }
    }
    __syncthreads();   // all xs reads done before overwrite

    // ---------------- Cross-group reduce + epilogue ----------------
    unsigned long long* sred = (unsigned long long*)xs_raw;   // 16 KB overlay
    if (g == 1) {
        #pragma unroll
        for (int p = 0; p < RPB / 2; p++) sred[p * 128 + t] = acc[p];
    }
    __syncthreads();
    if (g == 0) {
        const float bv = b0[t];
        #pragma unroll
        for (int p = 0; p < RPB / 2; p++) {
            float lo, hi, lo2, hi2;
            unpack2(acc[p], lo, hi);
            unpack2(sred[p * 128 + t], lo2, hi2);
            const size_t row = (size_t)row0 + 2 * p;
            g_L0[row * HIDDEN + t]       = fmaxf(lo + lo2 + bv, 0.f);
            g_L0[(row + 1) * HIDDEN + t] = fmaxf(hi + hi2 + bv, 0.f);
        }
    }
}

// ============================================================================
// Kernel 2: per root node b:
//   mean_t = ( sum_j 0.5*(neigh_original[b,j,t] - history[neighs1[b,j],t])
//            + sum_i history[h_nodes[b,i],t] ) / 15
//   y = [h1[b] | mean];  out[b] = relu(y @ W1 + b1)
// 128 blocks x 256 threads, 8 roots/block, W1 staged in smem (read once per
// block instead of once per root), 8 concurrent accumulators, 4-way split-K.
// Dynamic smem: 80 KB.
// ============================================================================
__global__ __launch_bounds__(256)
void final_kernel(const float* __restrict__ history,
                  const float* __restrict__ W1,
                  const float* __restrict__ b1,
                  const int*   __restrict__ neighs1,
                  const int*   __restrict__ h_nodes,
                  float*       __restrict__ out)
{
    extern __shared__ float sm[];
    float* W1s = sm;                        // 2*HIDDEN*NCLASS = 16384 floats (64 KB)
    float* ys  = sm + 2 * HIDDEN * NCLASS;  // FB*256 = 2048 floats
    float* red = ys + FB * 2 * HIDDEN;      // FB*4*64 = 2048 floats

    const int t   = threadIdx.x;
    const int b0r = blockIdx.x * FB;

    // Stage W1 (coalesced float4)
    for (int i = t; i < (2 * HIDDEN * NCLASS) / 4; i += 256)
        ((float4*)W1s)[i] = ((const float4*)W1)[i];

    // h1 halves of ys
    for (int i = t; i < FB * HIDDEN; i += 256) {
        const int r = i >> 7, c = i & 127;
        ys[r * 2 * HIDDEN + c] = g_L0[(size_t)(b0r + r) * HIDDEN + c];
    }

    // mean halves: each 128-thread half handles alternating roots
    {
        const int half = t >> 7;
        const int tc   = t & 127;
        #pragma unroll 1
        for (int rr = 0; rr < FB / 2; rr++) {
            const int r = rr * 2 + half;
            const int b = b0r + r;
            float s = 0.f;
            #pragma unroll
            for (int j = 0; j < K1; j++) {
                const int n1 = neighs1[b * K1 + j];
                const float no = g_L0[(size_t)(BATCH + b * K1 + j) * HIDDEN + tc];
                s += 0.5f * (no - history[(size_t)n1 * HIDDEN + tc]);  // * (N_HIST/K1)
            }
            #pragma unroll
            for (int j = 0; j < NHIST; j++) {
                const int hn = h_nodes[b * NHIST + j];
                s += history[(size_t)hn * HIDDEN + tc];
            }
            ys[r * 2 * HIDDEN + HIDDEN + tc] = s * (1.f / (K1 + NHIST));
        }
    }
    __syncthreads();

    // GEMV: o = class, s4 = k-slice; 8 roots concurrently per thread
    const int o  = t & 63;
    const int s4 = t >> 6;
    float acc[FB];
    #pragma unroll
    for (int r = 0; r < FB; r++) acc[r] = 0.f;
    #pragma unroll 4
    for (int kk = 0; kk < (2 * HIDDEN) / 4; kk++) {
        const int k = s4 * ((2 * HIDDEN) / 4) + kk;
        const float w = W1s[k * NCLASS + o];             // conflict-free
        #pragma unroll
        for (int r = 0; r < FB; r++)
            acc[r] += ys[r * 2 * HIDDEN + k] * w;        // smem broadcast
    }
    #pragma unroll
    for (int r = 0; r < FB; r++) red[(r * 4 + s4) * 64 + o] = acc[r];
    __syncthreads();

    for (int i = t; i < FB * NCLASS; i += 256) {
        const int r = i >> 6, o2 = i & 63;
        const float v = red[(r * 4 + 0) * 64 + o2] + red[(r * 4 + 1) * 64 + o2]
                      + red[(r * 4 + 2) * 64 + o2] + red[(r * 4 + 3) * 64 + o2];
        out[(size_t)(b0r + r) * NCLASS + o2] = fmaxf(v + b1[o2], 0.f);
    }
}

// ============================================================================
// kernel_launch — graph-capturable, allocation-free.
// Input order per metadata: feats, history, W0, b0, W1, b1, nodes, neighs0,
// neighs1, neighs0_nb, h_nodes. Output: float32 [1024, 64].
// ============================================================================
extern "C" void kernel_launch(void* const* d_in, const int* in_sizes, int n_in,
                              void* d_out, int out_size)
{
    const float* feats      = (const float*)d_in[0];
    const float* history    = (const float*)d_in[1];
    const float* W0         = (const float*)d_in[2];
    const float* b0         = (const float*)d_in[3];
    const float* W1         = (const float*)d_in[4];
    const float* b1         = (const float*)d_in[5];
    const int*   nodes      = (const int*)d_in[6];
    const int*   neighs0    = (const int*)d_in[7];
    const int*   neighs1    = (const int*)d_in[8];
    const int*   neighs0_nb = (const int*)d_in[9];
    const int*   h_nodes    = (const int*)d_in[10];
    float* out = (float*)d_out;

    // >48KB static smem is disallowed; opt in to large dynamic smem each call
    // (host-side attribute set, not a stream op — capture-safe, no allocation).
    cudaFuncSetAttribute(layer0_kernel, cudaFuncAttributeMaxDynamicSharedMemorySize,
                         16 * 2 * NFEATS * (int)sizeof(float2));           // 64 KB
    cudaFuncSetAttribute(final_kernel, cudaFuncAttributeMaxDynamicSharedMemorySize,
                         (2 * HIDDEN * NCLASS + FB * 2 * HIDDEN + FB * 4 * 64)
                             * (int)sizeof(float));                         // 80 KB

    w0pack_kernel<<<128, 256>>>(W0);
    layer0_kernel<<<NBLK, 256, 16 * 2 * NFEATS * sizeof(float2)>>>(
        feats, b0, nodes, neighs0, neighs1, neighs0_nb);
    final_kernel<<<FNBLK, 256,
                   (2 * HIDDEN * NCLASS + FB * 2 * HIDDEN + FB * 4 * 64) * sizeof(float)>>>(
        history, W1, b1, neighs1, h_nodes, out);
}